// round 11
// baseline (speedup 1.0000x reference)
#include <cuda_runtime.h>

// Single-layer LSTM, T=4096, B=1024, I=H=4, seq-first, zero init state.
// 4 lanes per batch element; 128 blocks x 32 threads -> 1 warp per SM.
//
// R9: issue-order surgery. The step is pure latency-chain bound (R7 proved
// issue pressure is irrelevant), so:
//  - shuffles of h issue IMMEDIATELY after h is produced (chain head starts
//    at +4 instead of +28);
//  - the output store and the NEXT step's input projection (packed f32x2,
//    12 instrs ~ 24 cyc) fill the 26-cyc shuffle window;
//  - recurrent tree is scalar FFMA consuming shuffle results directly
//    (no pack/unpack movs on the chain);
//  - tanh issue order (f,i,g,o) matches consumption order so MUFU rt=8
//    issue spread hides inside result latency.
// Activations: MUFU.TANH; sigmoid(x) = 0.5 + 0.5*tanh(x/2) with the 0.5
// pre-folded into sigmoid-row weights.

#define TLEN   4096
#define BATCH  1024
#define OUTSTRIDE (BATCH * 4)
#define UNROLL 8

typedef unsigned long long u64;

__device__ __forceinline__ float tanhf_a(float x) {
    float y; asm("tanh.approx.f32 %0, %1;" : "=f"(y) : "f"(x)); return y;
}
__device__ __forceinline__ u64 pack2(float lo, float hi) {
    u64 r; asm("mov.b64 %0, {%1, %2};" : "=l"(r) : "f"(lo), "f"(hi)); return r;
}
__device__ __forceinline__ void unpack2(float& lo, float& hi, u64 v) {
    asm("mov.b64 {%0, %1}, %2;" : "=f"(lo), "=f"(hi) : "l"(v));
}
__device__ __forceinline__ u64 fma2(u64 a, u64 b, u64 c) {
    u64 r; asm("fma.rn.f32x2 %0, %1, %2, %3;" : "=l"(r) : "l"(a), "l"(b), "l"(c)); return r;
}
__device__ __forceinline__ float shfl_bfly(float v, int m) {
    float y;
    asm volatile("shfl.sync.bfly.b32 %0, %1, %2, 0x1f, 0xffffffff;"
                 : "=f"(y) : "f"(v), "r"(m));
    return y;
}

__global__ void __launch_bounds__(32, 1)
lstm_recur(const float* __restrict__ input,
           const float* __restrict__ W_ih,
           const float* __restrict__ W_hh,
           const float* __restrict__ b_ih,
           const float* __restrict__ b_hh,
           float* __restrict__ out)
{
    const int g = blockIdx.x * 32 + threadIdx.x;   // 0..4095
    const int b = g >> 2;                          // batch element
    const int j = g & 3;                           // hidden unit owned by lane

    // PyTorch gate rows for unit j: i=j, f=4+j, g=8+j, o=12+j.
    // Sigmoid gates (i,f,o) pre-scaled 0.5; tanh gate (g) unscaled.
    // W_hh columns xor-permuted: shfl_xor(h, m) multiplies column (j^m).
    const int ri = j, rf = 4 + j, rg = 8 + j, ro = 12 + j;

    // Scalar recurrent weights (on-chain consumers).
    float uF[4], uI[4], uG[4], uO[4];
#pragma unroll
    for (int m = 0; m < 4; ++m) {
        const int mc = j ^ m;
        uF[m] = W_hh[rf * 4 + mc] * 0.5f;
        uI[m] = W_hh[ri * 4 + mc] * 0.5f;
        uG[m] = W_hh[rg * 4 + mc];
        uO[m] = W_hh[ro * 4 + mc] * 0.5f;
    }
    // Packed projection weights (off-chain filler): A=(F,I), B=(G,O).
    u64 wA[4], wB[4];
#pragma unroll
    for (int m = 0; m < 4; ++m) {
        wA[m] = pack2(W_ih[rf * 4 + m] * 0.5f, W_ih[ri * 4 + m] * 0.5f);
        wB[m] = pack2(W_ih[rg * 4 + m],        W_ih[ro * 4 + m] * 0.5f);
    }
    const u64 biasA = pack2((b_ih[rf] + b_hh[rf]) * 0.5f,
                            (b_ih[ri] + b_hh[ri]) * 0.5f);
    const u64 biasB = pack2((b_ih[rg] + b_hh[rg]),
                            (b_ih[ro] + b_hh[ro]) * 0.5f);

    const float4* __restrict__ xin = reinterpret_cast<const float4*>(input) + b;

    // 8-deep software prefetch (double buffer): covers 577-cyc DRAM latency.
    float4 xbuf[UNROLL], xnxt[UNROLL];
#pragma unroll
    for (int u = 0; u < UNROLL; ++u) xbuf[u] = xin[u * BATCH];

    float h = 0.0f, c = 0.0f;
    float h1 = 0.0f, h2 = 0.0f, h3 = 0.0f;    // shuffled partner h (h==0 at t=0)
    float pF, pI, pG, pO;                      // projection for current step
    {
        const u64 x0p = pack2(xbuf[0].x, xbuf[0].x);
        const u64 x1p = pack2(xbuf[0].y, xbuf[0].y);
        const u64 x2p = pack2(xbuf[0].z, xbuf[0].z);
        const u64 x3p = pack2(xbuf[0].w, xbuf[0].w);
        u64 pA = fma2(x0p, wA[0], biasA);
        u64 pB = fma2(x0p, wB[0], biasB);
        pA = fma2(x1p, wA[1], pA);  pB = fma2(x1p, wB[1], pB);
        pA = fma2(x2p, wA[2], pA);  pB = fma2(x2p, wB[2], pB);
        pA = fma2(x3p, wA[3], pA);  pB = fma2(x3p, wB[3], pB);
        unpack2(pF, pI, pA);
        unpack2(pG, pO, pB);
    }

    float* op = out + g;

#pragma unroll 1
    for (int t0 = 0; t0 < TLEN; t0 += UNROLL) {
#pragma unroll
        for (int u = 0; u < UNROLL; ++u) {
            int tp = t0 + UNROLL + u;
            tp = (tp < TLEN) ? tp : (TLEN - 1);
            xnxt[u] = xin[tp * BATCH];
        }

#pragma unroll
        for (int u = 0; u < UNROLL; ++u) {
            // ---- Recurrent tree (scalar; F first — its result is needed
            //      first on the c-path). h1..h3 arrived via last step's shfls.
            float aF = fmaf(h, uF[0], pF);
            float aI = fmaf(h, uI[0], pI);
            float aG = fmaf(h, uG[0], pG);
            float aO = fmaf(h, uO[0], pO);
            aF = fmaf(h1, uF[1], aF);
            aI = fmaf(h1, uI[1], aI);
            aG = fmaf(h1, uG[1], aG);
            aO = fmaf(h1, uO[1], aO);
            float bF = h2 * uF[2];
            float bI = h2 * uI[2];
            float bG = h2 * uG[2];
            float bO = h2 * uO[2];
            bF = fmaf(h3, uF[3], bF);
            bI = fmaf(h3, uI[3], bI);
            bG = fmaf(h3, uG[3], bG);
            bO = fmaf(h3, uO[3], bO);
            aF += bF;  aI += bI;  aG += bG;  aO += bO;

            // ---- Activations; issue order matches consumption order. ----
            const float tf = tanhf_a(aF);
            const float ti = tanhf_a(aI);
            const float tg = tanhf_a(aG);
            const float to = tanhf_a(aO);

            const float sf  = fmaf(tf, 0.5f, 0.5f);
            const float sfc = sf * c;
            const float si  = fmaf(ti, 0.5f, 0.5f);
            c = fmaf(si, tg, sfc);
            const float tc = tanhf_a(c);
            const float so = fmaf(to, 0.5f, 0.5f);
            h = so * tc;

            // ---- Chain head: shuffles issue IMMEDIATELY after h. ----
            h1 = shfl_bfly(h, 1);
            h2 = shfl_bfly(h, 2);
            h3 = shfl_bfly(h, 3);

            // ---- Fillers inside the 26-cyc shuffle window. ----
            op[(t0 + u) * OUTSTRIDE] = h;              // coalesced store

            {   // projection for the NEXT step (packed: 12 instrs ~ 24 cyc)
                const int un = (u + 1) & (UNROLL - 1);
                const float4 xv = (u + 1 < UNROLL) ? xbuf[un] : xnxt[0];
                const u64 x0p = pack2(xv.x, xv.x);
                const u64 x1p = pack2(xv.y, xv.y);
                const u64 x2p = pack2(xv.z, xv.z);
                const u64 x3p = pack2(xv.w, xv.w);
                u64 pA = fma2(x0p, wA[0], biasA);
                u64 pB = fma2(x0p, wB[0], biasB);
                pA = fma2(x1p, wA[1], pA);  pB = fma2(x1p, wB[1], pB);
                pA = fma2(x2p, wA[2], pA);  pB = fma2(x2p, wB[2], pB);
                pA = fma2(x3p, wA[3], pA);  pB = fma2(x3p, wB[3], pB);
                unpack2(pF, pI, pA);
                unpack2(pG, pO, pB);
            }
        }

#pragma unroll
        for (int u = 0; u < UNROLL; ++u) xbuf[u] = xnxt[u];
    }
}

extern "C" void kernel_launch(void* const* d_in, const int* in_sizes, int n_in,
                              void* d_out, int out_size)
{
    const float* input = (const float*)d_in[0];
    const float* W_ih  = (const float*)d_in[1];
    const float* W_hh  = (const float*)d_in[2];
    const float* b_ih  = (const float*)d_in[3];
    const float* b_hh  = (const float*)d_in[4];
    float* out = (float*)d_out;

    lstm_recur<<<128, 32>>>(input, W_ih, W_hh, b_ih, b_hh, out);
}